// round 5
// baseline (speedup 1.0000x reference)
#include <cuda_runtime.h>
#include <math.h>

#define F 128
#define NHEADS 8
#define SCALE 0.25f            // 1/sqrt(16)
#define MAXN 50048
#define MAXE 640064
#define OFFM (MAXN*NHEADS)

// ---------------- device scratch (static: no allocations allowed) ----------
__device__ float    g_q  [MAXN*F];          // q = node_h@Wq^T+bq
__device__ float    g_v  [MAXN*F];          // v = node_h@Wv^T+bv
__device__ float    g_Lin[MAXE*NHEADS];     // scaled logits
__device__ float    g_Lou[MAXE*NHEADS];
__device__ float    g_Ldg[MAXE*NHEADS];
__device__ float    g_att[MAXE];            // distance^lambda
__device__ unsigned g_M  [3*OFFM];          // flip-encoded segment max
__device__ float    g_Mf [3*OFFM];          // decoded max
__device__ float    g_D  [3*OFFM];          // segment sum of exp
__device__ float    g_Di [3*OFFM];          // 1/D
__device__ float    g_S  [OFFM];            // per (node,head) score sum

// ---------------- helpers ---------------------------------------------------
__device__ __forceinline__ void ffma2(unsigned long long &c,
                                      unsigned long long a,
                                      unsigned long long b) {
    // packed f32x2 FMA (Blackwell): 2 FMAs per instruction
    asm("fma.rn.f32x2 %0, %1, %2, %0;" : "+l"(c) : "l"(a), "l"(b));
}
__device__ __forceinline__ float pairsum(unsigned long long u) {
    float x, y;
    asm("mov.b64 {%0,%1}, %2;" : "=f"(x), "=f"(y) : "l"(u));
    return x + y;
}
__device__ __forceinline__ unsigned flipf(float x) {
    unsigned u = __float_as_uint(x);
    return (u >> 31) ? ~u : (u | 0x80000000u);   // monotone map float->uint
}
__device__ __forceinline__ float unflipf(unsigned u) {
    return (u >> 31) ? __uint_as_float(u ^ 0x80000000u) : __uint_as_float(~u);
}

// shared layout (floats): sW[128*132] | sA[64*132] | sBias[128]
#define PW 132
#define SW_ELEMS (128*PW)
#define SA_ELEMS (64*PW)
#define SMEM_FLOATS (SW_ELEMS + SA_ELEMS + 128)

__device__ __forceinline__ void load_W(const float* __restrict__ W,
                                       const float* __restrict__ bias,
                                       float* sW, float* sB, int tid) {
#pragma unroll
    for (int j = 0; j < 16; j++) {
        int idx = j * 256 + tid;
        int r = idx >> 5, c4 = idx & 31;
        *(float4*)(sW + r * PW + c4 * 4) = *(const float4*)(W + r * 128 + c4 * 4);
    }
    if (tid < 128) sB[tid] = bias[tid];
}

// core 64x128x128 tile GEMM with f32x2 packed FMAs.
// thread tile: 8 rows x 4 cols (cols tc, tc+32, tc+64, tc+96)
__device__ __forceinline__ void gemm_compute(const float* sA, const float* sW,
                                             int tid, unsigned long long (&acc)[8][4]) {
    int tc = tid & 31, trg = tid >> 5;
#pragma unroll
    for (int r = 0; r < 8; r++)
#pragma unroll
        for (int c = 0; c < 4; c++) acc[r][c] = 0ull;
    const float* aB = sA + trg * 8 * PW;
#pragma unroll 4
    for (int i = 0; i < 128; i += 4) {
        ulonglong2 a2[8], b2[4];
#pragma unroll
        for (int r = 0; r < 8; r++)
            a2[r] = *(const ulonglong2*)(aB + r * PW + i);      // broadcast in warp
#pragma unroll
        for (int c = 0; c < 4; c++)
            b2[c] = *(const ulonglong2*)(sW + (tc + 32 * c) * PW + i);  // conflict-free
#pragma unroll
        for (int r = 0; r < 8; r++)
#pragma unroll
            for (int c = 0; c < 4; c++) {
                ffma2(acc[r][c], a2[r].x, b2[c].x);   // even/odd k partial sums
                ffma2(acc[r][c], a2[r].y, b2[c].y);
            }
    }
}

// ---------------- kernels ---------------------------------------------------

// q / v projection: C = A @ W^T + b  ->  g_q (which=0) or g_v (which=1)
__global__ void __launch_bounds__(256) gemm_qv_kernel(const float* __restrict__ A,
                                                      const float* __restrict__ W,
                                                      const float* __restrict__ bias,
                                                      int Mrows, int which) {
    extern __shared__ float sm[];
    float* sW = sm; float* sA = sm + SW_ELEMS; float* sB = sA + SA_ELEMS;
    int tid = threadIdx.x; int row0 = blockIdx.x * 64;
    load_W(W, bias, sW, sB, tid);
#pragma unroll
    for (int j = 0; j < 8; j++) {
        int idx = j * 256 + tid; int r = idx >> 5, c4 = idx & 31;
        int gr = row0 + r;
        float4 a = make_float4(0.f, 0.f, 0.f, 0.f);
        if (gr < Mrows) a = *(const float4*)(A + (size_t)gr * 128 + c4 * 4);
        *(float4*)(sA + r * PW + c4 * 4) = a;
    }
    __syncthreads();
    unsigned long long acc[8][4];
    gemm_compute(sA, sW, tid, acc);
    int tc = tid & 31, trg = tid >> 5;
    float* C = which ? g_v : g_q;
#pragma unroll
    for (int r = 0; r < 8; r++) {
        int gr = row0 + trg * 8 + r;
        if (gr < Mrows) {
#pragma unroll
            for (int c = 0; c < 4; c++) {
                int col = tc + 32 * c;
                C[(size_t)gr * 128 + col] = pairsum(acc[r][c]) + sB[col];
            }
        }
    }
}

// fused: k = edge_h@Wk^T+bk (kept in smem) + edge attention logits
__global__ void __launch_bounds__(256) k_logits_kernel(const float* __restrict__ edge_h,
                                                       const float* __restrict__ Wk,
                                                       const float* __restrict__ bk,
                                                       const int* __restrict__ src,
                                                       const int* __restrict__ dst,
                                                       int E) {
    extern __shared__ float sm[];
    float* sW = sm; float* sA = sm + SW_ELEMS; float* sB = sA + SA_ELEMS;
    int tid = threadIdx.x; int row0 = blockIdx.x * 64;
    load_W(Wk, bk, sW, sB, tid);
#pragma unroll
    for (int j = 0; j < 8; j++) {
        int idx = j * 256 + tid; int r = idx >> 5, c4 = idx & 31;
        int ge = row0 + r;
        float4 a = make_float4(0.f, 0.f, 0.f, 0.f);
        if (ge < E) a = *(const float4*)(edge_h + (size_t)ge * 128 + c4 * 4);
        *(float4*)(sA + r * PW + c4 * 4) = a;
    }
    __syncthreads();
    unsigned long long acc[8][4];
    gemm_compute(sA, sW, tid, acc);
    __syncthreads();                       // everyone done reading sA
    int tc = tid & 31, trg = tid >> 5;
#pragma unroll
    for (int r = 0; r < 8; r++)
#pragma unroll
        for (int c = 0; c < 4; c++) {
            int col = tc + 32 * c;
            sA[(trg * 8 + r) * PW + col] = pairsum(acc[r][c]) + sB[col];  // k tile
        }
    __syncthreads();
    // logits: one work item per (edge-in-tile, head)
    for (int w = tid; w < 64 * NHEADS; w += 256) {
        int et = w >> 3, h = w & 7;
        int e = row0 + et;
        if (e < E) {
            int s = src[e], d = dst[e];
            const float4* qs = (const float4*)(g_q + (size_t)s * 128 + h * 16);
            const float4* qd = (const float4*)(g_q + (size_t)d * 128 + h * 16);
            const float4* kk = (const float4*)(sA + et * PW + h * 16);
            float im = 0.f, om = 0.f, dg = 0.f;
#pragma unroll
            for (int j = 0; j < 4; j++) {
                float4 a = qs[j], b = qd[j], c = kk[j];
                im += a.x * c.x + a.y * c.y + a.z * c.z + a.w * c.w;
                om += b.x * c.x + b.y * c.y + b.z * c.z + b.w * c.w;
                dg += a.x * b.x + a.y * b.y + a.z * b.z + a.w * b.w;
            }
            size_t o = (size_t)e * NHEADS + h;
            g_Lin[o] = im * SCALE;
            g_Lou[o] = om * SCALE;
            g_Ldg[o] = dg * SCALE;
        }
    }
}

__global__ void init_kernel(const float* __restrict__ dist,
                            const float* __restrict__ lam, int E) {
    int t = blockIdx.x * blockDim.x + threadIdx.x;
    if (t < 3 * OFFM) { g_M[t] = 0u; g_D[t] = 0.f; }
    if (t < OFFM) g_S[t] = 0.f;
    if (t < E) g_att[t] = powf(dist[t], lam[0]);
}

__global__ void max_kernel(const int* __restrict__ dst, int E) {
    int t = blockIdx.x * blockDim.x + threadIdx.x;
    if (t >= E * NHEADS) return;
    int e = t >> 3, h = t & 7;
    int idx = dst[e] * NHEADS + h;
    atomicMax(&g_M[idx],            flipf(g_Lin[t]));
    atomicMax(&g_M[OFFM + idx],     flipf(g_Lou[t]));
    atomicMax(&g_M[2 * OFFM + idx], flipf(g_Ldg[t]));
}

__global__ void decode_kernel(int N) {
    int t = blockIdx.x * blockDim.x + threadIdx.x;
    if (t >= N * NHEADS) return;
#pragma unroll
    for (int k = 0; k < 3; k++) {
        unsigned u = g_M[k * OFFM + t];
        g_Mf[k * OFFM + t] = u ? unflipf(u) : 0.f;
    }
}

__global__ void sum_kernel(const int* __restrict__ dst, int E) {
    int t = blockIdx.x * blockDim.x + threadIdx.x;
    if (t >= E * NHEADS) return;
    int e = t >> 3, h = t & 7;
    int idx = dst[e] * NHEADS + h;
    atomicAdd(&g_D[idx],            expf(g_Lin[t] - g_Mf[idx]));
    atomicAdd(&g_D[OFFM + idx],     expf(g_Lou[t] - g_Mf[OFFM + idx]));
    atomicAdd(&g_D[2 * OFFM + idx], expf(g_Ldg[t] - g_Mf[2 * OFFM + idx]));
}

__global__ void recip_kernel(int N) {
    int t = blockIdx.x * blockDim.x + threadIdx.x;
    if (t >= N * NHEADS) return;
#pragma unroll
    for (int k = 0; k < 3; k++) {
        float d = g_D[k * OFFM + t];
        g_Di[k * OFFM + t] = (d != 0.f) ? 1.f / d : 0.f;
    }
}

__global__ void score_kernel(const int* __restrict__ dst, int E) {
    int t = blockIdx.x * blockDim.x + threadIdx.x;
    if (t >= E * NHEADS) return;
    int e = t >> 3, h = t & 7;
    int idx = dst[e] * NHEADS + h;
    float s = expf(g_Lin[t] - g_Mf[idx])            * g_Di[idx]
            + expf(g_Lou[t] - g_Mf[OFFM + idx])     * g_Di[OFFM + idx]
            + expf(g_Ldg[t] - g_Mf[2 * OFFM + idx]) * g_Di[2 * OFFM + idx];
    atomicAdd(&g_S[idx], s * g_att[e]);
}

// out = leaky_relu( (S ⊙ v) @ Wo^T + bo )
__global__ void __launch_bounds__(256) out_kernel(const float* __restrict__ Wo,
                                                  const float* __restrict__ bo,
                                                  float* __restrict__ out, int N) {
    extern __shared__ float sm[];
    float* sW = sm; float* sA = sm + SW_ELEMS; float* sB = sA + SA_ELEMS;
    int tid = threadIdx.x; int row0 = blockIdx.x * 64;
    load_W(Wo, bo, sW, sB, tid);
#pragma unroll
    for (int j = 0; j < 8; j++) {
        int idx = j * 256 + tid; int r = idx >> 5, c4 = idx & 31;
        int gr = row0 + r;
        float4 a = make_float4(0.f, 0.f, 0.f, 0.f);
        if (gr < N) {
            a = *(const float4*)(g_v + (size_t)gr * 128 + c4 * 4);
            float sc = g_S[gr * NHEADS + (c4 >> 2)];   // head = (c4*4)/16
            a.x *= sc; a.y *= sc; a.z *= sc; a.w *= sc;
        }
        *(float4*)(sA + r * PW + c4 * 4) = a;
    }
    __syncthreads();
    unsigned long long acc[8][4];
    gemm_compute(sA, sW, tid, acc);
    int tc = tid & 31, trg = tid >> 5;
#pragma unroll
    for (int r = 0; r < 8; r++) {
        int gr = row0 + trg * 8 + r;
        if (gr < N) {
#pragma unroll
            for (int c = 0; c < 4; c++) {
                int col = tc + 32 * c;
                float x = pairsum(acc[r][c]) + sB[col];
                out[(size_t)gr * 128 + col] = (x > 0.f) ? x : 0.1f * x;
            }
        }
    }
}

// ---------------- launch -----------------------------------------------------
extern "C" void kernel_launch(void* const* d_in, const int* in_sizes, int n_in,
                              void* d_out, int out_size) {
    const float* node_h   = (const float*)d_in[0];
    const float* edge_h   = (const float*)d_in[1];
    const float* distance = (const float*)d_in[2];
    const float* Wq = (const float*)d_in[3];  const float* bq = (const float*)d_in[4];
    const float* Wk = (const float*)d_in[5];  const float* bk = (const float*)d_in[6];
    const float* Wv = (const float*)d_in[7];  const float* bv = (const float*)d_in[8];
    const float* Wo = (const float*)d_in[9];  const float* bo = (const float*)d_in[10];
    const float* lam = (const float*)d_in[11];
    const int*   src = (const int*)d_in[12];
    const int*   dst = (const int*)d_in[13];

    int N = in_sizes[0] / F;
    int E = in_sizes[12];
    float* out = (float*)d_out;

    size_t smemB = SMEM_FLOATS * sizeof(float);   // ~99.5 KB
    cudaFuncSetAttribute(gemm_qv_kernel, cudaFuncAttributeMaxDynamicSharedMemorySize, (int)smemB);
    cudaFuncSetAttribute(k_logits_kernel, cudaFuncAttributeMaxDynamicSharedMemorySize, (int)smemB);
    cudaFuncSetAttribute(out_kernel, cudaFuncAttributeMaxDynamicSharedMemorySize, (int)smemB);

    int ib = (3 * OFFM + 255) / 256;
    init_kernel<<<ib, 256>>>(distance, lam, E);

    int nb = (N + 63) / 64;
    gemm_qv_kernel<<<nb, 256, smemB>>>(node_h, Wq, bq, N, 0);
    gemm_qv_kernel<<<nb, 256, smemB>>>(node_h, Wv, bv, N, 1);

    int eb = (E + 63) / 64;
    k_logits_kernel<<<eb, 256, smemB>>>(edge_h, Wk, bk, src, dst, E);

    int tb = (E * NHEADS + 255) / 256;
    int db = (N * NHEADS + 255) / 256;
    max_kernel<<<tb, 256>>>(dst, E);
    decode_kernel<<<db, 256>>>(N);
    sum_kernel<<<tb, 256>>>(dst, E);
    recip_kernel<<<db, 256>>>(N);
    score_kernel<<<tb, 256>>>(dst, E);

    out_kernel<<<nb, 256, smemB>>>(Wo, bo, out, N);
}